// round 11
// baseline (speedup 1.0000x reference)
#include <cuda_runtime.h>
#include <math_constants.h>

// Sparsemax along last dim. (64,1024,512) fp32 -> 65536 rows x 512.
// Persistent warps, 2048 blocks x 4 warps = 8192 warps, 8 rows/warp.
// Pipeline trick: after candidate compaction the z registers are DEAD for
// the Newton phase (candidates live in smem), so the NEXT row is prefetched
// into the same z buffer (zero extra registers, unlike naive prefetch).
// The epilogue re-reads the current row from L2 (just fetched; in-flight
// working set ~14MB << 126MB L2) and writes relu(x - tau).
// tau >= max-1 => candidates are x > max-1 (~6/row). Newton on
// f(tau)=sum(relu(x-tau))-1 from tau0=max-1, monotone, exact on PW-linear f.
// sm_103: integer redux.sync only; (count,sum) packed in one u32 redux.

#define N_COLS 512
#define WPB    4                   // warps per block (128-thread blocks)
#define NBLK   2048                // 2048*4 = 8192 warps -> 8 rows/warp
#define QSCALE 1048576.0f          // 2^20
#define QINV   (1.0f/1048576.0f)

__device__ __forceinline__ unsigned fkey(float x) {
    unsigned b = __float_as_uint(x);
    return b ^ (unsigned)(((int)b >> 31) | 0x80000000);
}
__device__ __forceinline__ float funkey(unsigned k) {
    unsigned m = (unsigned)((~((int)k >> 31)) | 0x80000000);
    return __uint_as_float(k ^ m);
}

__global__ __launch_bounds__(128) void sparsemax_kernel(
    const float* __restrict__ x, float* __restrict__ out, int rows)
{
    __shared__ float cand[WPB][32];

    const int wib  = threadIdx.x >> 5;
    const int lane = threadIdx.x & 31;
    const unsigned lt_mask = (1u << lane) - 1u;

    const int wg     = blockIdx.x * WPB + wib;
    const int stride = gridDim.x * WPB;
    if (wg >= rows) return;

    const float4* __restrict__ inb = reinterpret_cast<const float4*>(x);
    float4*       __restrict__ opb = reinterpret_cast<float4*>(out);

    // Preload first row (default caching: line must survive in L2 for the
    // epilogue re-read).
    float z[16];
    {
        const float4* p = inb + (size_t)wg * (N_COLS / 4);
        #pragma unroll
        for (int i = 0; i < 4; i++) {
            float4 v = p[i * 32 + lane];
            z[i*4+0] = v.x; z[i*4+1] = v.y; z[i*4+2] = v.z; z[i*4+3] = v.w;
        }
    }

    for (int r = wg; r < rows; r += stride) {
        const float4* pr = inb + (size_t)r * (N_COLS / 4);

        // ---- warp max of current row ----
        float ml = -CUDART_INF_F;
        #pragma unroll
        for (int i = 0; i < 16; i++) ml = fmaxf(ml, z[i]);
        const float m   = funkey(__reduce_max_sync(0xffffffffu, fkey(ml)));
        const float thr = m - 1.0f;              // tau >= thr always

        // ---- ballot-compact candidates (z > thr) into smem (cap 32) ----
        float s0l = 0.0f;
        int cnt = 0;
        #pragma unroll
        for (int i = 0; i < 16; i++) {
            bool p = z[i] > thr;
            unsigned b = __ballot_sync(0xffffffffu, p);
            if (p) {
                s0l += z[i] - thr;
                int pos = (cnt + __popc(b & lt_mask)) & 31;
                cand[wib][pos] = z[i];
            }
            cnt += __popc(b);
        }
        unsigned s0i = __reduce_add_sync(0xffffffffu,
                                         __float2uint_rn(s0l * QSCALE));
        float s0 = (float)s0i * QINV;            // >= 1 (max contributes 1)
        __syncwarp();                            // STS -> LDS visibility

        // ---- z is now dead: prefetch NEXT row into it (overlaps Newton) ----
        const int rn = r + stride;
        if (rn < rows) {
            const float4* pn = inb + (size_t)rn * (N_COLS / 4);
            #pragma unroll
            for (int i = 0; i < 4; i++) {
                float4 v = pn[i * 32 + lane];
                z[i*4+0] = v.x; z[i*4+1] = v.y; z[i*4+2] = v.z; z[i*4+3] = v.w;
            }
        }

        // ---- Newton: tau1 = thr + (s0-1)/cnt, then iterate on candidates --
        float tau = thr + __fdividef(s0 - 1.0f, (float)cnt);

        if (cnt <= 32) {
            float c = (lane < cnt) ? cand[wib][lane] : -CUDART_INF_F;
            #pragma unroll 1
            for (int it = 0; it < 32; it++) {
                float t = c - tau;
                bool  p = t > 0.0f;
                unsigned packed = (p ? (1u << 26) : 0u)
                                + __float2uint_rn(fmaxf(t, 0.0f) * QSCALE);
                unsigned rr = __reduce_add_sync(0xffffffffu, packed);
                unsigned k = rr >> 26;
                if (k == 0) break;
                float s  = (float)(rr & 0x03ffffffu) * QINV;
                float tn = tau + __fdividef(s - 1.0f, (float)k);
                if (!(tn > tau + 1e-6f)) {       // quantization floor
                    tau = fmaxf(tau, tn);
                    break;
                }
                tau = tn;
            }
        } else {
            // degenerate rows: z holds the NEXT row now, so re-read the
            // current row from L2 each iteration (rare; correctness only).
            #pragma unroll 1
            for (int it = 0; it < 64; it++) {
                float sl = 0.0f; int kl = 0;
                #pragma unroll
                for (int i = 0; i < 4; i++) {
                    float4 v = __ldg(&pr[i * 32 + lane]);
                    float t;
                    t = v.x - tau; if (t > 0.0f) { sl += t; kl++; }
                    t = v.y - tau; if (t > 0.0f) { sl += t; kl++; }
                    t = v.z - tau; if (t > 0.0f) { sl += t; kl++; }
                    t = v.w - tau; if (t > 0.0f) { sl += t; kl++; }
                }
                unsigned si = __reduce_add_sync(0xffffffffu,
                                                __float2uint_rn(sl * QSCALE));
                int k = __reduce_add_sync(0xffffffffu, (unsigned)kl);
                if (k == 0) break;
                float s  = (float)si * QINV;
                float tn = tau + __fdividef(s - 1.0f, (float)k);
                if (!(tn > tau)) break;
                tau = tn;
            }
        }

        // ---- epilogue: re-read current row from L2, relu(x - tau), store --
        {
            float4* po = opb + (size_t)r * (N_COLS / 4);
            #pragma unroll
            for (int i = 0; i < 4; i++) {
                float4 v = __ldg(&pr[i * 32 + lane]);   // L2 hit
                float4 w;
                w.x = fmaxf(v.x - tau, 0.0f);
                w.y = fmaxf(v.y - tau, 0.0f);
                w.z = fmaxf(v.z - tau, 0.0f);
                w.w = fmaxf(v.w - tau, 0.0f);
                __stcs(&po[i * 32 + lane], w);
            }
        }
    }
}

extern "C" void kernel_launch(void* const* d_in, const int* in_sizes, int n_in,
                              void* d_out, int out_size)
{
    const float* x = (const float*)d_in[0];
    float* out = (float*)d_out;
    const int n = in_sizes[0];
    const int rows = n / N_COLS;

    int blocks = NBLK;
    int max_blocks = (rows + WPB - 1) / WPB;
    if (blocks > max_blocks) blocks = max_blocks;
    sparsemax_kernel<<<blocks, 32 * WPB>>>(x, out, rows);
}

// round 12
// speedup vs baseline: 1.1255x; 1.1255x over previous
#include <cuda_runtime.h>
#include <math_constants.h>

// Sparsemax along last dim. (64,1024,512) fp32 -> 65536 rows x 512.
// One warp per row, 16 fp32/lane (4x float4, __ldcs). tau >= max-1 =>
// candidates are x > max-1 (~6/row gaussian). Ballot-compact into a 32-entry
// per-warp smem buffer (clamped index); Newton on f(tau)=sum(relu(x-tau))-1
// from tau0=max-1 (monotone from below, exact on piecewise-linear f).
// sm_103: integer redux.sync only -> warp max via monotone uint key;
// Newton (count,sum) in ONE u32 redux: (k<<26)|round(t*2^20).
// Epilogue subtraction uses packed add.rn.f32x2 (Blackwell f32x2 pipe).
// Block = 64 threads (2 warps): finest CTA granularity for wave balance and
// minimal per-CTA L1tex front-batched load queue depth.

#define N_COLS 512
#define WARPS_PER_BLOCK 2          // 64-thread blocks
#define QSCALE 1048576.0f          // 2^20
#define QINV   (1.0f/1048576.0f)

__device__ __forceinline__ unsigned fkey(float x) {
    unsigned b = __float_as_uint(x);
    return b ^ (unsigned)(((int)b >> 31) | 0x80000000);
}
__device__ __forceinline__ float funkey(unsigned k) {
    unsigned m = (unsigned)((~((int)k >> 31)) | 0x80000000);
    return __uint_as_float(k ^ m);
}

__global__ __launch_bounds__(64) void sparsemax_kernel(
    const float* __restrict__ x, float* __restrict__ out, int rows)
{
    __shared__ float cand[WARPS_PER_BLOCK][32];

    const int wib  = threadIdx.x >> 5;
    const int row  = blockIdx.x * WARPS_PER_BLOCK + wib;
    if (row >= rows) return;
    const int lane = threadIdx.x & 31;
    const unsigned lt_mask = (1u << lane) - 1u;

    const float4* __restrict__ in = reinterpret_cast<const float4*>(x   + (size_t)row * N_COLS);
    float4*       __restrict__ op = reinterpret_cast<float4*>(      out + (size_t)row * N_COLS);

    float z[16];
    float ml = -CUDART_INF_F;
    #pragma unroll
    for (int i = 0; i < 4; i++) {
        float4 v = __ldcs(&in[i * 32 + lane]);   // streaming: evict-first
        z[i*4+0] = v.x; z[i*4+1] = v.y; z[i*4+2] = v.z; z[i*4+3] = v.w;
        ml = fmaxf(ml, fmaxf(fmaxf(v.x, v.y), fmaxf(v.z, v.w)));
    }
    const float m   = funkey(__reduce_max_sync(0xffffffffu, fkey(ml)));
    const float thr = m - 1.0f;                  // tau >= thr always

    // Ballot-compact candidates (z > thr) into smem (index clamped to 31;
    // fast path only used when cnt <= 32 so the clamp is harmless).
    // s0 = sum(z-thr) accumulated alongside for a free first Newton step.
    float s0l = 0.0f;
    int cnt = 0;
    #pragma unroll
    for (int i = 0; i < 16; i++) {
        bool p = z[i] > thr;
        unsigned b = __ballot_sync(0xffffffffu, p);
        if (p) {
            s0l += z[i] - thr;
            int pos = (cnt + __popc(b & lt_mask)) & 31;
            cand[wib][pos] = z[i];
        }
        cnt += __popc(b);
    }
    unsigned s0i = __reduce_add_sync(0xffffffffu,
                                     __float2uint_rn(s0l * QSCALE));
    float s0 = (float)s0i * QINV;                // >= 1 (max contributes 1)
    __syncwarp();                                // STS -> LDS visibility

    // First Newton update: tau1 = thr + (s0-1)/cnt (monotone from below)
    float tau = thr + __fdividef(s0 - 1.0f, (float)cnt);

    if (cnt <= 32) {
        float c = (lane < cnt) ? cand[wib][lane] : -CUDART_INF_F;
        #pragma unroll 1
        for (int it = 0; it < 32; it++) {
            float t = c - tau;
            bool  p = t > 0.0f;
            unsigned packed = (p ? (1u << 26) : 0u)
                            + __float2uint_rn(fmaxf(t, 0.0f) * QSCALE);
            unsigned r = __reduce_add_sync(0xffffffffu, packed);
            unsigned k = r >> 26;
            if (k == 0) break;
            float s  = (float)(r & 0x03ffffffu) * QINV;
            float tn = tau + __fdividef(s - 1.0f, (float)k);
            if (!(tn > tau + 1e-6f)) {           // quantization floor reached
                tau = fmaxf(tau, tn);
                break;
            }
            tau = tn;
        }
    } else {
        // degenerate rows (many near-max values): rescan registers
        #pragma unroll 1
        for (int it = 0; it < 64; it++) {
            float sl = 0.0f; int kl = 0;
            #pragma unroll
            for (int i = 0; i < 16; i++) {
                float t = z[i] - tau;
                if (t > 0.0f) { sl += t; kl++; }
            }
            unsigned si = __reduce_add_sync(0xffffffffu,
                                            __float2uint_rn(sl * QSCALE));
            int k = __reduce_add_sync(0xffffffffu, (unsigned)kl);
            if (k == 0) break;
            float s  = (float)si * QINV;
            float tn = tau + __fdividef(s - 1.0f, (float)k);
            if (!(tn > tau)) break;
            tau = tn;
        }
    }

    // Epilogue: packed f32x2 subtraction (8 ops for 16 elems), scalar relu.
    unsigned long long ntau2;
    {
        unsigned nt = __float_as_uint(-tau);
        asm("mov.b64 %0, {%1, %1};" : "=l"(ntau2) : "r"(nt));
    }
    #pragma unroll
    for (int i = 0; i < 4; i++) {
        float t0, t1, t2, t3;
        unsigned long long pa, pb, qa, qb;
        asm("mov.b64 %0, {%1, %2};" : "=l"(pa)
            : "f"(z[i*4+0]), "f"(z[i*4+1]));
        asm("mov.b64 %0, {%1, %2};" : "=l"(pb)
            : "f"(z[i*4+2]), "f"(z[i*4+3]));
        asm("add.rn.f32x2 %0, %1, %2;" : "=l"(qa) : "l"(pa), "l"(ntau2));
        asm("add.rn.f32x2 %0, %1, %2;" : "=l"(qb) : "l"(pb), "l"(ntau2));
        asm("mov.b64 {%0, %1}, %2;" : "=f"(t0), "=f"(t1) : "l"(qa));
        asm("mov.b64 {%0, %1}, %2;" : "=f"(t2), "=f"(t3) : "l"(qb));
        float4 v;
        v.x = fmaxf(t0, 0.0f);
        v.y = fmaxf(t1, 0.0f);
        v.z = fmaxf(t2, 0.0f);
        v.w = fmaxf(t3, 0.0f);
        __stcs(&op[i * 32 + lane], v);
    }
}

extern "C" void kernel_launch(void* const* d_in, const int* in_sizes, int n_in,
                              void* d_out, int out_size)
{
    const float* x = (const float*)d_in[0];
    float* out = (float*)d_out;
    const int n = in_sizes[0];
    const int rows = n / N_COLS;

    const int threads = 32 * WARPS_PER_BLOCK;
    const int blocks = (rows + WARPS_PER_BLOCK - 1) / WARPS_PER_BLOCK;
    sparsemax_kernel<<<blocks, threads>>>(x, out, rows);
}

// round 13
// speedup vs baseline: 1.1408x; 1.0136x over previous
#include <cuda_runtime.h>
#include <math_constants.h>

// Sparsemax along last dim. (64,1024,512) fp32 -> 65536 rows x 512.
// One warp per row, 16 fp32/lane (4x float4, __ldcs). tau >= max-1 =>
// candidates are x > max-1 (~6/row gaussian). Ballot-compact into a 32-entry
// per-warp smem buffer (clamped index); Newton on f(tau)=sum(relu(x-tau))-1
// from tau0 = max-1 (monotone from below, exact on piecewise-linear f);
// the FIRST loop iteration doubles as the s0/cnt bootstrap step.
// sm_103: integer redux.sync only -> warp max via monotone uint key;
// Newton (count,sum) in ONE u32 redux: (k<<26)|round(t*2^20)
// (fast path: t in (0,1], sum <= 32 < 64 -> no carry into k field).
// Epilogue subtraction uses packed add.rn.f32x2. 64-thread blocks (best
// measured geometry: finest wave granularity at full occupancy).

#define N_COLS 512
#define WARPS_PER_BLOCK 2          // 64-thread blocks
#define QSCALE 1048576.0f          // 2^20
#define QINV   (1.0f/1048576.0f)

__device__ __forceinline__ unsigned fkey(float x) {
    unsigned b = __float_as_uint(x);
    return b ^ (unsigned)(((int)b >> 31) | 0x80000000);
}
__device__ __forceinline__ float funkey(unsigned k) {
    unsigned m = (unsigned)((~((int)k >> 31)) | 0x80000000);
    return __uint_as_float(k ^ m);
}

__global__ __launch_bounds__(64) void sparsemax_kernel(
    const float* __restrict__ x, float* __restrict__ out, int rows)
{
    __shared__ float cand[WARPS_PER_BLOCK][32];

    const int wib  = threadIdx.x >> 5;
    const int row  = blockIdx.x * WARPS_PER_BLOCK + wib;
    if (row >= rows) return;
    const int lane = threadIdx.x & 31;
    const unsigned lt_mask = (1u << lane) - 1u;

    const float4* __restrict__ in = reinterpret_cast<const float4*>(x   + (size_t)row * N_COLS);
    float4*       __restrict__ op = reinterpret_cast<float4*>(      out + (size_t)row * N_COLS);

    float z[16];
    float ml = -CUDART_INF_F;
    #pragma unroll
    for (int i = 0; i < 4; i++) {
        float4 v = __ldcs(&in[i * 32 + lane]);   // streaming: evict-first
        z[i*4+0] = v.x; z[i*4+1] = v.y; z[i*4+2] = v.z; z[i*4+3] = v.w;
        ml = fmaxf(ml, fmaxf(fmaxf(v.x, v.y), fmaxf(v.z, v.w)));
    }
    const float m   = funkey(__reduce_max_sync(0xffffffffu, fkey(ml)));
    const float thr = m - 1.0f;                  // tau >= thr always

    // Ballot-compact candidates (z > thr) into smem (index clamped to 31;
    // fast path only used when cnt <= 32 so the clamp is harmless).
    int cnt = 0;
    #pragma unroll
    for (int i = 0; i < 16; i++) {
        bool p = z[i] > thr;
        unsigned b = __ballot_sync(0xffffffffu, p);
        if (p) {
            int pos = (cnt + __popc(b & lt_mask)) & 31;
            cand[wib][pos] = z[i];
        }
        cnt += __popc(b);
    }
    __syncwarp();                                // STS -> LDS visibility

    // Newton from tau0 = thr; the first iteration IS the s0/cnt step
    // (k = cnt, s = sum(c - thr) >= 1 since the max contributes exactly 1).
    float tau = thr;

    if (cnt <= 32) {
        float c = (lane < cnt) ? cand[wib][lane] : -CUDART_INF_F;
        #pragma unroll 1
        for (int it = 0; it < 32; it++) {
            float t = c - tau;
            bool  p = t > 0.0f;
            unsigned packed = (p ? (1u << 26) : 0u)
                            + __float2uint_rn(fmaxf(t, 0.0f) * QSCALE);
            unsigned r = __reduce_add_sync(0xffffffffu, packed);
            unsigned k = r >> 26;
            if (k == 0) break;
            float s  = (float)(r & 0x03ffffffu) * QINV;
            float tn = tau + __fdividef(s - 1.0f, (float)k);
            if (!(tn > tau + 1e-6f)) {           // quantization floor reached
                tau = fmaxf(tau, tn);
                break;
            }
            tau = tn;
        }
    } else {
        // degenerate rows (many near-max values): rescan registers
        #pragma unroll 1
        for (int it = 0; it < 64; it++) {
            float sl = 0.0f; int kl = 0;
            #pragma unroll
            for (int i = 0; i < 16; i++) {
                float t = z[i] - tau;
                if (t > 0.0f) { sl += t; kl++; }
            }
            unsigned si = __reduce_add_sync(0xffffffffu,
                                            __float2uint_rn(sl * QSCALE));
            int k = __reduce_add_sync(0xffffffffu, (unsigned)kl);
            if (k == 0) break;
            float s  = (float)si * QINV;
            float tn = tau + __fdividef(s - 1.0f, (float)k);
            if (!(tn > tau)) break;
            tau = tn;
        }
    }

    // Epilogue: packed f32x2 subtraction (8 ops for 16 elems), scalar relu.
    unsigned long long ntau2;
    {
        unsigned nt = __float_as_uint(-tau);
        asm("mov.b64 %0, {%1, %1};" : "=l"(ntau2) : "r"(nt));
    }
    #pragma unroll
    for (int i = 0; i < 4; i++) {
        float t0, t1, t2, t3;
        unsigned long long pa, pb, qa, qb;
        asm("mov.b64 %0, {%1, %2};" : "=l"(pa)
            : "f"(z[i*4+0]), "f"(z[i*4+1]));
        asm("mov.b64 %0, {%1, %2};" : "=l"(pb)
            : "f"(z[i*4+2]), "f"(z[i*4+3]));
        asm("add.rn.f32x2 %0, %1, %2;" : "=l"(qa) : "l"(pa), "l"(ntau2));
        asm("add.rn.f32x2 %0, %1, %2;" : "=l"(qb) : "l"(pb), "l"(ntau2));
        asm("mov.b64 {%0, %1}, %2;" : "=f"(t0), "=f"(t1) : "l"(qa));
        asm("mov.b64 {%0, %1}, %2;" : "=f"(t2), "=f"(t3) : "l"(qb));
        float4 v;
        v.x = fmaxf(t0, 0.0f);
        v.y = fmaxf(t1, 0.0f);
        v.z = fmaxf(t2, 0.0f);
        v.w = fmaxf(t3, 0.0f);
        __stcs(&op[i * 32 + lane], v);
    }
}

extern "C" void kernel_launch(void* const* d_in, const int* in_sizes, int n_in,
                              void* d_out, int out_size)
{
    const float* x = (const float*)d_in[0];
    float* out = (float*)d_out;
    const int n = in_sizes[0];
    const int rows = n / N_COLS;

    const int threads = 32 * WARPS_PER_BLOCK;
    const int blocks = (rows + WARPS_PER_BLOCK - 1) / WARPS_PER_BLOCK;
    sparsemax_kernel<<<blocks, threads>>>(x, out, rows);
}